// round 8
// baseline (speedup 1.0000x reference)
#include <cuda_runtime.h>
#include <cuda_bf16.h>
#include <math_constants.h>
#include <mma.h>

using namespace nvcuda;

#define N_NODES   262144
#define D_IN      512
#define B_GRAPHS  256
#define GATES     2048      // 4*D_IN
#define K_COMB    1024      // combined K (h:512 | r:512)
#define STEPS     6
#define CHUNK     1772      // nodes per attention block (148 blocks = 1 wave @ 1 CTA/SM)
#define N_CHUNKS  ((N_NODES + CHUNK - 1) / CHUNK)   // 148
#define MAX_SLOTS 8
#define TILE      32        // nodes per smem tile (64 KB per buffer)

// ----------------- device scratch (no runtime allocation allowed) -----------
__device__ __align__(16) float g_W[GATES * K_COMB];     // combined weights, tf32-rounded
__device__ __align__(16) float g_bias[GATES];           // b_ih + b_hh
__device__ __align__(16) float g_hr[B_GRAPHS * 1024];   // [h | r] = q_star layout
__device__ __align__(16) float g_c[B_GRAPHS * D_IN];
__device__ __align__(16) float g_gates[B_GRAPHS * GATES];
__device__ int   g_off[B_GRAPHS + 1];
// attention partials: per (graph, slot)
__device__ __align__(16) float g_part_r[B_GRAPHS * MAX_SLOTS * D_IN];
__device__ float g_part_m[B_GRAPHS * MAX_SLOTS];
__device__ float g_part_d[B_GRAPHS * MAX_SLOTS];

// ----------------------------- helpers --------------------------------------
__device__ __forceinline__ float sigm(float v) {
    return 1.0f / (1.0f + __expf(-v));
}
__device__ __forceinline__ float tf32r(float v) {
    unsigned u;
    asm("cvt.rna.tf32.f32 %0, %1;" : "=r"(u) : "f"(v));
    return __uint_as_float(u);
}
__device__ __forceinline__ void cp_async16(void* smem_dst, const void* gmem_src) {
    unsigned s = (unsigned)__cvta_generic_to_shared(smem_dst);
    asm volatile("cp.async.cg.shared.global [%0], [%1], 16;" :: "r"(s), "l"(gmem_src));
}
#define CP_COMMIT() asm volatile("cp.async.commit_group;")
#define CP_WAIT1()  asm volatile("cp.async.wait_group 1;")
#define CP_WAIT0()  asm volatile("cp.async.wait_group 0;")

// --------------------------- prep kernels -----------------------------------
__global__ void prep_w_kernel(const float* __restrict__ w_ih,
                              const float* __restrict__ w_hh,
                              const float* __restrict__ b_ih,
                              const float* __restrict__ b_hh) {
    int idx = blockIdx.x * blockDim.x + threadIdx.x;   // 0 .. 2048*1024-1
    int n = idx >> 10;
    int k = idx & 1023;
    float v = w_ih[n * 1024 + k];
    if (k < 512) v += w_hh[n * 512 + k];
    g_W[idx] = tf32r(v);
    if (idx < GATES) g_bias[idx] = b_ih[idx] + b_hh[idx];
}

// batch is int32, sorted ascending in [0, B). g_off[t] = lower_bound(batch, t).
__global__ void offsets_kernel(const int* __restrict__ batch) {
    int t = blockIdx.x * blockDim.x + threadIdx.x;
    if (t > B_GRAPHS) return;
    int lo = 0, hi = N_NODES;
    while (lo < hi) {
        int mid = (lo + hi) >> 1;
        if (batch[mid] < t) lo = mid + 1; else hi = mid;
    }
    g_off[t] = lo;
}

// Step 0: q_star = 0, h = 0  ->  gates = bias (identical for every graph)
__global__ void lstm_init_kernel() {
    int b = blockIdx.x;          // 256
    int d = threadIdx.x;         // 512
    float i = sigm(g_bias[d]);
    float g = tanhf(g_bias[1024 + d]);
    float o = sigm(g_bias[1536 + d]);
    float c = i * g;
    g_c[b * D_IN + d]  = c;
    g_hr[b * 1024 + d] = o * tanhf(c);
}

// ----------------- GEMM (tf32 tensor cores): gates = hr @ W^T ----------------
// M=256, N=2048, K=1024. CTA tile 64x64, 8 warps, warp = 1x2 wmma 16x16 tiles.
__global__ void __launch_bounds__(256) gemm_tc_kernel() {
    __shared__ __align__(16) float sA[64][40];
    __shared__ __align__(16) float sB[64][40];

    const int bm = blockIdx.y * 64;        // gridDim.y = 4
    const int bn = blockIdx.x * 64;        // gridDim.x = 32
    const int tid = threadIdx.x;
    const int w   = tid >> 5;              // warp 0..7
    const int mt  = w & 3;                 // M-tile 0..3
    const int ng  = w >> 2;                // N-group 0..1

    wmma::fragment<wmma::accumulator, 16, 16, 8, float> cf[2];
    wmma::fill_fragment(cf[0], 0.0f);
    wmma::fill_fragment(cf[1], 0.0f);

    const int row = tid >> 2;              // 0..63
    const int col = (tid & 3) * 8;         // 0,8,16,24

    const float* Ag = g_hr + (bm + row) * K_COMB + col;
    const float* Bg = g_W  + (bn + row) * K_COMB + col;

    float4 a0 = *(const float4*)(Ag);
    float4 a1 = *(const float4*)(Ag + 4);
    float4 b0 = *(const float4*)(Bg);
    float4 b1 = *(const float4*)(Bg + 4);

    for (int k0 = 0; k0 < K_COMB; k0 += 32) {
        sA[row][col + 0] = tf32r(a0.x); sA[row][col + 1] = tf32r(a0.y);
        sA[row][col + 2] = tf32r(a0.z); sA[row][col + 3] = tf32r(a0.w);
        sA[row][col + 4] = tf32r(a1.x); sA[row][col + 5] = tf32r(a1.y);
        sA[row][col + 6] = tf32r(a1.z); sA[row][col + 7] = tf32r(a1.w);
        sB[row][col + 0] = b0.x; sB[row][col + 1] = b0.y;
        sB[row][col + 2] = b0.z; sB[row][col + 3] = b0.w;
        sB[row][col + 4] = b1.x; sB[row][col + 5] = b1.y;
        sB[row][col + 6] = b1.z; sB[row][col + 7] = b1.w;
        __syncthreads();

        if (k0 + 32 < K_COMB) {
            a0 = *(const float4*)(Ag + k0 + 32);
            a1 = *(const float4*)(Ag + k0 + 36);
            b0 = *(const float4*)(Bg + k0 + 32);
            b1 = *(const float4*)(Bg + k0 + 36);
        }

        #pragma unroll
        for (int kk = 0; kk < 32; kk += 8) {
            wmma::fragment<wmma::matrix_a, 16, 16, 8, wmma::precision::tf32, wmma::row_major> af;
            wmma::load_matrix_sync(af, &sA[mt * 16][kk], 40);
            #pragma unroll
            for (int t = 0; t < 2; t++) {
                wmma::fragment<wmma::matrix_b, 16, 16, 8, wmma::precision::tf32, wmma::col_major> bf;
                wmma::load_matrix_sync(bf, &sB[(ng * 2 + t) * 16][kk], 40);
                wmma::mma_sync(cf[t], af, bf, cf[t]);
            }
        }
        __syncthreads();
    }

    #pragma unroll
    for (int t = 0; t < 2; t++)
        wmma::store_matrix_sync(&g_gates[(bm + mt * 16) * GATES + bn + (ng * 2 + t) * 16],
                                cf[t], GATES, wmma::mem_row_major);
}

// --------------------------- LSTM pointwise (adds bias) ----------------------
__global__ void lstm_pw_kernel() {
    int idx = blockIdx.x * blockDim.x + threadIdx.x;   // 0 .. 131071
    int b = idx >> 9;
    int d = idx & 511;
    const float* gr = g_gates + b * GATES + d;
    float i = sigm(gr[0]    + g_bias[d]);
    float f = sigm(gr[512]  + g_bias[512 + d]);
    float g = tanhf(gr[1024] + g_bias[1024 + d]);
    float o = sigm(gr[1536] + g_bias[1536 + d]);
    float c = f * g_c[idx] + i * g;
    g_c[idx] = c;
    g_hr[b * 1024 + d] = o * tanhf(c);     // q = h into hr[:, :512]
}

// ------------- attention pass 1: cp.async double-buffered tiles --------------
// 148 blocks (one wave @ 1 CTA/SM, 128KB dynamic smem). While tile t is
// computed from buffer cur, tile t+1 streams into buffer cur^1 via cp.async.
__global__ void __launch_bounds__(512, 1) attn_chunk_kernel(const float* __restrict__ x) {
    extern __shared__ __align__(16) float4 sm_buf[];   // 2 * TILE * 128 float4
    __shared__ __align__(16) float sm_q[D_IN];
    __shared__ float sm_e[TILE];
    __shared__ __align__(16) float sm_w[TILE];
    __shared__ float sm_scale;

    const int chunk = blockIdx.x;
    const int i0 = chunk * CHUNK;
    const int i1 = min(i0 + CHUNK, N_NODES);
    const int tid  = threadIdx.x;
    const int wid  = tid >> 5;
    const int lane = tid & 31;
    const float4* x4 = (const float4*)x;

    // first graph whose segment intersects [i0, i1)
    int lo = 0, hi = B_GRAPHS;
    while (lo < hi) {
        int mid = (lo + hi) >> 1;
        if (g_off[mid + 1] <= i0) lo = mid + 1; else hi = mid;
    }
    int b = lo;

    while (b < B_GRAPHS && g_off[b] < i1) {
        const int s0 = max(g_off[b], i0);
        const int s1 = min(g_off[b + 1], i1);
        if (s1 > s0) {
            sm_q[tid] = g_hr[b * 1024 + tid];
            __syncthreads();
            float4 qv[4];
            #pragma unroll
            for (int j = 0; j < 4; j++) qv[j] = ((const float4*)sm_q)[j * 32 + lane];

            float r_acc = 0.0f;
            float m = -CUDART_INF_F, denom = 0.0f;   // meaningful in warp 0

            // prefetch first tile into buffer 0
            {
                const int F = min(TILE, s1 - s0) * 128;
                #pragma unroll
                for (int k = 0; k < 8; k++) {
                    int f = tid + k * 512;
                    if (f < F) cp_async16(sm_buf + f, x4 + (size_t)s0 * 128 + f);
                }
            }
            CP_COMMIT();

            int cur = 0;
            for (int t = s0; t < s1; t += TILE) {
                const int T = min(TILE, s1 - t);
                const bool has_next = (t + TILE) < s1;
                if (has_next) {
                    float4* dst = sm_buf + ((cur ^ 1) * TILE * 128);
                    const int Fn = min(TILE, s1 - (t + TILE)) * 128;
                    #pragma unroll
                    for (int k = 0; k < 8; k++) {
                        int f = tid + k * 512;
                        if (f < Fn) cp_async16(dst + f, x4 + (size_t)(t + TILE) * 128 + f);
                    }
                    CP_COMMIT();
                    CP_WAIT1();           // current tile done, next in flight
                } else {
                    CP_WAIT0();
                }
                __syncthreads();

                const float4* bx  = sm_buf + (cur * TILE * 128);
                const float*  bxf = (const float*)bx;

                // ---- logits: warp w -> nodes w, w+16 ----
                #pragma unroll
                for (int rep = 0; rep < 2; rep++) {
                    const int n = wid + rep * 16;
                    if (n < T) {
                        const float4* row = bx + n * 128;
                        float p = 0.0f;
                        #pragma unroll
                        for (int j = 0; j < 4; j++) {
                            float4 v = row[j * 32 + lane];
                            p = fmaf(v.x, qv[j].x, p);
                            p = fmaf(v.y, qv[j].y, p);
                            p = fmaf(v.z, qv[j].z, p);
                            p = fmaf(v.w, qv[j].w, p);
                        }
                        #pragma unroll
                        for (int o = 16; o; o >>= 1)
                            p += __shfl_xor_sync(0xffffffffu, p, o);
                        if (lane == 0) sm_e[n] = p;
                    }
                }
                __syncthreads();

                // ---- warp 0: online softmax bookkeeping ----
                if (wid == 0) {
                    float e = (lane < T) ? sm_e[lane] : -CUDART_INF_F;
                    float tmax = e;
                    #pragma unroll
                    for (int o = 16; o; o >>= 1)
                        tmax = fmaxf(tmax, __shfl_xor_sync(0xffffffffu, tmax, o));
                    const float mn = fmaxf(m, tmax);
                    const float w  = (lane < T) ? __expf(e - mn) : 0.0f;
                    sm_w[lane] = w;
                    float ws = w;
                    #pragma unroll
                    for (int o = 16; o; o >>= 1)
                        ws += __shfl_xor_sync(0xffffffffu, ws, o);
                    const float sc = __expf(m - mn);  // first tile: exp(-inf)=0
                    denom = fmaf(denom, sc, ws);
                    m = mn;
                    if (lane == 0) sm_scale = sc;
                }
                __syncthreads();

                // ---- accumulate: thread owns column tid ----
                r_acc *= sm_scale;
                if (T == TILE) {
                    #pragma unroll
                    for (int n4 = 0; n4 < TILE / 4; n4++) {
                        float4 w4 = ((const float4*)sm_w)[n4];
                        r_acc = fmaf(w4.x, bxf[(n4*4+0) * 512 + tid], r_acc);
                        r_acc = fmaf(w4.y, bxf[(n4*4+1) * 512 + tid], r_acc);
                        r_acc = fmaf(w4.z, bxf[(n4*4+2) * 512 + tid], r_acc);
                        r_acc = fmaf(w4.w, bxf[(n4*4+3) * 512 + tid], r_acc);
                    }
                } else {
                    for (int n = 0; n < T; n++)
                        r_acc = fmaf(sm_w[n], bxf[n * 512 + tid], r_acc);
                }
                __syncthreads();   // tile consumed; its buffer may be re-filled
                cur ^= 1;
            }

            const int slot = chunk - g_off[b] / CHUNK;
            g_part_r[(b * MAX_SLOTS + slot) * D_IN + tid] = r_acc;
            if (tid == 0) {
                g_part_m[b * MAX_SLOTS + slot] = m;
                g_part_d[b * MAX_SLOTS + slot] = denom;
            }
            __syncthreads();   // protect sm_q before next segment
        }
        b++;
    }
}

// ------------------ attention pass 2: per-graph merge ------------------------
__global__ void attn_merge_kernel() {
    const int b   = blockIdx.x;      // 256
    const int tid = threadIdx.x;     // 512
    const int o0 = g_off[b], o1 = g_off[b + 1];
    if (o1 <= o0) { g_hr[b * 1024 + 512 + tid] = 0.0f; return; }
    const int J = (o1 - 1) / CHUNK - o0 / CHUNK + 1;   // <= MAX_SLOTS

    float M = -CUDART_INF_F;
    for (int j = 0; j < J; j++) M = fmaxf(M, g_part_m[b * MAX_SLOTS + j]);
    float D = 0.0f, acc = 0.0f;
    for (int j = 0; j < J; j++) {
        const float s = __expf(g_part_m[b * MAX_SLOTS + j] - M);
        D   = fmaf(g_part_d[b * MAX_SLOTS + j], s, D);
        acc = fmaf(g_part_r[(b * MAX_SLOTS + j) * D_IN + tid], s, acc);
    }
    g_hr[b * 1024 + 512 + tid] = acc / (D + 1e-16f);
}

// ------------------------------- output --------------------------------------
__global__ void copyout_kernel(float* __restrict__ out) {
    int idx = blockIdx.x * blockDim.x + threadIdx.x;   // 0 .. 262143
    out[idx] = g_hr[idx];
}

// ------------------------------- launch --------------------------------------
extern "C" void kernel_launch(void* const* d_in, const int* in_sizes, int n_in,
                              void* d_out, int out_size) {
    const float* x     = (const float*)d_in[0];
    const int*   batch = (const int*)d_in[1];
    const float* w_ih  = (const float*)d_in[2];
    const float* w_hh  = (const float*)d_in[3];
    const float* b_ih  = (const float*)d_in[4];
    const float* b_hh  = (const float*)d_in[5];
    float* out = (float*)d_out;

    const int attn_smem = 2 * TILE * D_IN * sizeof(float);   // 128 KB
    cudaFuncSetAttribute(attn_chunk_kernel,
                         cudaFuncAttributeMaxDynamicSharedMemorySize, attn_smem);

    prep_w_kernel<<<(GATES * K_COMB) / 256, 256>>>(w_ih, w_hh, b_ih, b_hh);
    offsets_kernel<<<2, 160>>>(batch);
    lstm_init_kernel<<<B_GRAPHS, 512>>>();

    for (int s = 0; s < STEPS; s++) {
        if (s > 0) {
            gemm_tc_kernel<<<dim3(32, 4), 256>>>();
            lstm_pw_kernel<<<(B_GRAPHS * D_IN) / 512, 512>>>();
        }
        attn_chunk_kernel<<<N_CHUNKS, 512, attn_smem>>>(x);
        attn_merge_kernel<<<B_GRAPHS, 512>>>();
    }
    copyout_kernel<<<(B_GRAPHS * 1024) / 256, 256>>>(out);
}

// round 9
// speedup vs baseline: 1.5779x; 1.5779x over previous
#include <cuda_runtime.h>
#include <cuda_fp16.h>
#include <math_constants.h>
#include <mma.h>

using namespace nvcuda;

#define N_NODES   262144
#define D_IN      512
#define B_GRAPHS  256
#define GATES     2048      // 4*D_IN
#define K_COMB    1024      // combined K (h:512 | r:512)
#define STEPS     6
#define CHUNK     896       // nodes per attention block (293 blocks = 1 wave @ 2 CTA/SM)
#define N_CHUNKS  ((N_NODES + CHUNK - 1) / CHUNK)   // 293
#define MAX_SLOTS 8

// ----------------- device scratch (no runtime allocation allowed) -----------
__device__ __align__(16) float  g_W[GATES * K_COMB];
__device__ __align__(16) float  g_bias[GATES];
__device__ __align__(16) float  g_hr[B_GRAPHS * 1024];    // [h | r] = q_star
__device__ __align__(16) float  g_c[B_GRAPHS * D_IN];
__device__ __align__(16) float  g_gates[B_GRAPHS * GATES];
__device__ __align__(16) __half g_x16[(size_t)N_NODES * D_IN];  // 256 MB fp16 copy
__device__ int g_off[B_GRAPHS + 1];
__device__ __align__(16) float g_part_r[B_GRAPHS * MAX_SLOTS * D_IN];
__device__ float g_part_m[B_GRAPHS * MAX_SLOTS];
__device__ float g_part_d[B_GRAPHS * MAX_SLOTS];

// ----------------------------- helpers --------------------------------------
__device__ __forceinline__ float sigm(float v) {
    return 1.0f / (1.0f + __expf(-v));
}
__device__ __forceinline__ float tf32r(float v) {
    unsigned u;
    asm("cvt.rna.tf32.f32 %0, %1;" : "=r"(u) : "f"(v));
    return __uint_as_float(u);
}

// --------------------------- prep kernels -----------------------------------
__global__ void prep_w_kernel(const float* __restrict__ w_ih,
                              const float* __restrict__ w_hh,
                              const float* __restrict__ b_ih,
                              const float* __restrict__ b_hh) {
    int idx = blockIdx.x * blockDim.x + threadIdx.x;
    int n = idx >> 10;
    int k = idx & 1023;
    float v = w_ih[n * 1024 + k];
    if (k < 512) v += w_hh[n * 512 + k];
    g_W[idx] = tf32r(v);
    if (idx < GATES) g_bias[idx] = b_ih[idx] + b_hh[idx];
}

__global__ void offsets_kernel(const int* __restrict__ batch) {
    int t = blockIdx.x * blockDim.x + threadIdx.x;
    if (t > B_GRAPHS) return;
    int lo = 0, hi = N_NODES;
    while (lo < hi) {
        int mid = (lo + hi) >> 1;
        if (batch[mid] < t) lo = mid + 1; else hi = mid;
    }
    g_off[t] = lo;
}

// Step 0: q_star = 0, h = 0 -> gates = bias (identical for every graph)
__global__ void lstm_init_kernel() {
    int b = blockIdx.x;
    int d = threadIdx.x;
    float i = sigm(g_bias[d]);
    float g = tanhf(g_bias[1024 + d]);
    float o = sigm(g_bias[1536 + d]);
    float c = i * g;
    g_c[b * D_IN + d]  = c;
    g_hr[b * 1024 + d] = o * tanhf(c);
}

// ----------------- GEMM (tf32 tensor cores): gates = hr @ W^T ----------------
__global__ void __launch_bounds__(256) gemm_tc_kernel() {
    __shared__ __align__(16) float sA[64][40];
    __shared__ __align__(16) float sB[64][40];

    const int bm = blockIdx.y * 64;
    const int bn = blockIdx.x * 64;
    const int tid = threadIdx.x;
    const int w   = tid >> 5;
    const int mt  = w & 3;
    const int ng  = w >> 2;

    wmma::fragment<wmma::accumulator, 16, 16, 8, float> cf[2];
    wmma::fill_fragment(cf[0], 0.0f);
    wmma::fill_fragment(cf[1], 0.0f);

    const int row = tid >> 2;
    const int col = (tid & 3) * 8;

    const float* Ag = g_hr + (bm + row) * K_COMB + col;
    const float* Bg = g_W  + (bn + row) * K_COMB + col;

    float4 a0 = *(const float4*)(Ag);
    float4 a1 = *(const float4*)(Ag + 4);
    float4 b0 = *(const float4*)(Bg);
    float4 b1 = *(const float4*)(Bg + 4);

    for (int k0 = 0; k0 < K_COMB; k0 += 32) {
        sA[row][col + 0] = tf32r(a0.x); sA[row][col + 1] = tf32r(a0.y);
        sA[row][col + 2] = tf32r(a0.z); sA[row][col + 3] = tf32r(a0.w);
        sA[row][col + 4] = tf32r(a1.x); sA[row][col + 5] = tf32r(a1.y);
        sA[row][col + 6] = tf32r(a1.z); sA[row][col + 7] = tf32r(a1.w);
        sB[row][col + 0] = b0.x; sB[row][col + 1] = b0.y;
        sB[row][col + 2] = b0.z; sB[row][col + 3] = b0.w;
        sB[row][col + 4] = b1.x; sB[row][col + 5] = b1.y;
        sB[row][col + 6] = b1.z; sB[row][col + 7] = b1.w;
        __syncthreads();

        if (k0 + 32 < K_COMB) {
            a0 = *(const float4*)(Ag + k0 + 32);
            a1 = *(const float4*)(Ag + k0 + 36);
            b0 = *(const float4*)(Bg + k0 + 32);
            b1 = *(const float4*)(Bg + k0 + 36);
        }

        #pragma unroll
        for (int kk = 0; kk < 32; kk += 8) {
            wmma::fragment<wmma::matrix_a, 16, 16, 8, wmma::precision::tf32, wmma::row_major> af;
            wmma::load_matrix_sync(af, &sA[mt * 16][kk], 40);
            #pragma unroll
            for (int t = 0; t < 2; t++) {
                wmma::fragment<wmma::matrix_b, 16, 16, 8, wmma::precision::tf32, wmma::col_major> bf;
                wmma::load_matrix_sync(bf, &sB[(ng * 2 + t) * 16][kk], 40);
                wmma::mma_sync(cf[t], af, bf, cf[t]);
            }
        }
        __syncthreads();
    }

    #pragma unroll
    for (int t = 0; t < 2; t++)
        wmma::store_matrix_sync(&g_gates[(bm + mt * 16) * GATES + bn + (ng * 2 + t) * 16],
                                cf[t], GATES, wmma::mem_row_major);
}

// --------------------------- LSTM pointwise (adds bias) ----------------------
__global__ void lstm_pw_kernel() {
    int idx = blockIdx.x * blockDim.x + threadIdx.x;
    int b = idx >> 9;
    int d = idx & 511;
    const float* gr = g_gates + b * GATES + d;
    float i = sigm(gr[0]    + g_bias[d]);
    float f = sigm(gr[512]  + g_bias[512 + d]);
    float g = tanhf(gr[1024] + g_bias[1024 + d]);
    float o = sigm(gr[1536] + g_bias[1536 + d]);
    float c = f * g_c[idx] + i * g;
    g_c[idx] = c;
    g_hr[b * 1024 + d] = o * tanhf(c);
}

// ---------- attention step 0: fp32 sweep + write fp16 copy of x --------------
// R5 structure: warp-per-node online softmax; col layout slot j*4+c <->
// column 128*j + 4*lane + c. Also emits g_x16.
__global__ void __launch_bounds__(512, 2) attn0_kernel(const float* __restrict__ x) {
    const int chunk = blockIdx.x;
    const int i0 = chunk * CHUNK;
    const int i1 = min(i0 + CHUNK, N_NODES);
    const int tid  = threadIdx.x;
    const int wid  = tid >> 5;
    const int lane = tid & 31;

    __shared__ __align__(16) float sm_q[D_IN];
    __shared__ float  sm_m[16], sm_d[16], sm_scale[16];
    __shared__ __align__(16) float4 sm_r[16][128];

    int lo = 0, hi = B_GRAPHS;
    while (lo < hi) {
        int mid = (lo + hi) >> 1;
        if (g_off[mid + 1] <= i0) lo = mid + 1; else hi = mid;
    }
    int b = lo;

    while (b < B_GRAPHS && g_off[b] < i1) {
        const int s0 = max(g_off[b], i0);
        const int s1 = min(g_off[b + 1], i1);
        if (s1 > s0) {
            sm_q[tid] = g_hr[b * 1024 + tid];
            __syncthreads();
            const float4* q4 = (const float4*)sm_q;

            float m = -CUDART_INF_F, denom = 0.0f;
            float r[16];
            #pragma unroll
            for (int k = 0; k < 16; k++) r[k] = 0.0f;

            for (int n = s0 + wid; n < s1; n += 16) {
                const float4* xr = (const float4*)(x + (size_t)n * D_IN);
                float xv[16];
                #pragma unroll
                for (int j = 0; j < 4; j++) {
                    float4 v = __ldcs(xr + j * 32 + lane);
                    xv[j*4+0] = v.x; xv[j*4+1] = v.y;
                    xv[j*4+2] = v.z; xv[j*4+3] = v.w;
                }
                // write fp16 copy: cols 128j+4lane -> uint2 (two half2)
                {
                    uint2* row16 = (uint2*)(g_x16 + (size_t)n * D_IN);
                    #pragma unroll
                    for (int j = 0; j < 4; j++) {
                        __half2 h0 = __floats2half2_rn(xv[j*4+0], xv[j*4+1]);
                        __half2 h1 = __floats2half2_rn(xv[j*4+2], xv[j*4+3]);
                        uint2 px;
                        px.x = *(unsigned*)&h0;
                        px.y = *(unsigned*)&h1;
                        row16[j * 32 + lane] = px;
                    }
                }

                float p = 0.0f;
                #pragma unroll
                for (int j = 0; j < 4; j++) {
                    float4 qv = q4[j * 32 + lane];
                    p = fmaf(xv[j*4+0], qv.x, p);
                    p = fmaf(xv[j*4+1], qv.y, p);
                    p = fmaf(xv[j*4+2], qv.z, p);
                    p = fmaf(xv[j*4+3], qv.w, p);
                }
                #pragma unroll
                for (int o = 16; o; o >>= 1) p += __shfl_xor_sync(0xffffffffu, p, o);

                const float mn = fmaxf(m, p);
                const float sc = __expf(m - mn);
                const float wg = __expf(p - mn);
                denom = fmaf(denom, sc, wg);
                #pragma unroll
                for (int k = 0; k < 16; k++) r[k] = fmaf(r[k], sc, wg * xv[k]);
                m = mn;
            }

            if (lane == 0) { sm_m[wid] = m; sm_d[wid] = denom; }
            #pragma unroll
            for (int j = 0; j < 4; j++)
                sm_r[wid][j * 32 + lane] =
                    make_float4(r[j*4+0], r[j*4+1], r[j*4+2], r[j*4+3]);
            __syncthreads();

            float M = -CUDART_INF_F;
            #pragma unroll
            for (int w = 0; w < 16; w++) M = fmaxf(M, sm_m[w]);
            if (tid < 16)
                sm_scale[tid] = (sm_m[tid] == -CUDART_INF_F) ? 0.0f : __expf(sm_m[tid] - M);
            __syncthreads();

            float Dn = 0.0f, num = 0.0f;
            #pragma unroll
            for (int w = 0; w < 16; w++) {
                Dn  += sm_d[w] * sm_scale[w];
                num  = fmaf(((const float*)sm_r[w])[tid], sm_scale[w], num);
            }

            const int slot = chunk - g_off[b] / CHUNK;
            g_part_r[(b * MAX_SLOTS + slot) * D_IN + tid] = num;
            if (tid == 0) {
                g_part_m[b * MAX_SLOTS + slot] = M;
                g_part_d[b * MAX_SLOTS + slot] = Dn;
            }
            __syncthreads();
        }
        b++;
    }
}

// ---------- attention steps 1..5: fp16 sweep, 2 nodes per warp-iter ----------
// Lane owns cols [8*lane, 8*lane+8) and [256+8*lane, 256+8*lane+8).
__global__ void __launch_bounds__(512, 2) attn16_kernel() {
    const int chunk = blockIdx.x;
    const int i0 = chunk * CHUNK;
    const int i1 = min(i0 + CHUNK, N_NODES);
    const int tid  = threadIdx.x;
    const int wid  = tid >> 5;
    const int lane = tid & 31;

    __shared__ __align__(16) float sm_q[D_IN];
    __shared__ float  sm_m[16], sm_d[16], sm_scale[16];
    __shared__ __align__(16) float4 sm_r[16][128];

    int lo = 0, hi = B_GRAPHS;
    while (lo < hi) {
        int mid = (lo + hi) >> 1;
        if (g_off[mid + 1] <= i0) lo = mid + 1; else hi = mid;
    }
    int b = lo;

    while (b < B_GRAPHS && g_off[b] < i1) {
        const int s0 = max(g_off[b], i0);
        const int s1 = min(g_off[b + 1], i1);
        if (s1 > s0) {
            sm_q[tid] = g_hr[b * 1024 + tid];
            __syncthreads();
            // lane's q slice: float4s at idx 2lane, 2lane+1, 64+2lane, 64+2lane+1
            const float4* q4 = (const float4*)sm_q;
            float qf[16];
            {
                float4 a = q4[2*lane],   bq = q4[2*lane+1];
                float4 c = q4[64+2*lane], d = q4[64+2*lane+1];
                qf[0]=a.x; qf[1]=a.y; qf[2]=a.z; qf[3]=a.w;
                qf[4]=bq.x; qf[5]=bq.y; qf[6]=bq.z; qf[7]=bq.w;
                qf[8]=c.x; qf[9]=c.y; qf[10]=c.z; qf[11]=c.w;
                qf[12]=d.x; qf[13]=d.y; qf[14]=d.z; qf[15]=d.w;
            }

            float m = -CUDART_INF_F, denom = 0.0f;
            float r[16];
            #pragma unroll
            for (int k = 0; k < 16; k++) r[k] = 0.0f;

            for (int n = s0 + wid * 2; n < s1; n += 32) {
                const uint4* rowa = (const uint4*)(g_x16 + (size_t)n * D_IN);
                uint4 a0 = __ldcs(rowa + lane);
                uint4 a1 = __ldcs(rowa + 32 + lane);
                const bool has_b = (n + 1) < s1;
                uint4 b0, b1;
                if (has_b) {
                    const uint4* rowb = (const uint4*)(g_x16 + (size_t)(n + 1) * D_IN);
                    b0 = __ldcs(rowb + lane);
                    b1 = __ldcs(rowb + 32 + lane);
                }

                // ---- node a ----
                float xf[16];
                {
                    const unsigned* u = (const unsigned*)&a0;
                    #pragma unroll
                    for (int t = 0; t < 4; t++) {
                        float2 f = __half22float2(*(const __half2*)&u[t]);
                        xf[t*2+0] = f.x; xf[t*2+1] = f.y;
                    }
                    const unsigned* v = (const unsigned*)&a1;
                    #pragma unroll
                    for (int t = 0; t < 4; t++) {
                        float2 f = __half22float2(*(const __half2*)&v[t]);
                        xf[8+t*2+0] = f.x; xf[8+t*2+1] = f.y;
                    }
                }
                float p = 0.0f;
                #pragma unroll
                for (int k = 0; k < 16; k++) p = fmaf(xf[k], qf[k], p);
                #pragma unroll
                for (int o = 16; o; o >>= 1) p += __shfl_xor_sync(0xffffffffu, p, o);
                float mn = fmaxf(m, p);
                float sc = __expf(m - mn);
                float wg = __expf(p - mn);
                denom = fmaf(denom, sc, wg);
                #pragma unroll
                for (int k = 0; k < 16; k++) r[k] = fmaf(r[k], sc, wg * xf[k]);
                m = mn;

                // ---- node b ----
                if (has_b) {
                    float yf[16];
                    {
                        const unsigned* u = (const unsigned*)&b0;
                        #pragma unroll
                        for (int t = 0; t < 4; t++) {
                            float2 f = __half22float2(*(const __half2*)&u[t]);
                            yf[t*2+0] = f.x; yf[t*2+1] = f.y;
                        }
                        const unsigned* v = (const unsigned*)&b1;
                        #pragma unroll
                        for (int t = 0; t < 4; t++) {
                            float2 f = __half22float2(*(const __half2*)&v[t]);
                            yf[8+t*2+0] = f.x; yf[8+t*2+1] = f.y;
                        }
                    }
                    float pb = 0.0f;
                    #pragma unroll
                    for (int k = 0; k < 16; k++) pb = fmaf(yf[k], qf[k], pb);
                    #pragma unroll
                    for (int o = 16; o; o >>= 1) pb += __shfl_xor_sync(0xffffffffu, pb, o);
                    mn = fmaxf(m, pb);
                    sc = __expf(m - mn);
                    wg = __expf(pb - mn);
                    denom = fmaf(denom, sc, wg);
                    #pragma unroll
                    for (int k = 0; k < 16; k++) r[k] = fmaf(r[k], sc, wg * yf[k]);
                    m = mn;
                }
            }

            if (lane == 0) { sm_m[wid] = m; sm_d[wid] = denom; }
            // lane's cols: 8lane..8lane+7 and 256+8lane..+7
            {
                float* dst = (float*)sm_r[wid];
                dst[8*lane+0]=r[0]; dst[8*lane+1]=r[1]; dst[8*lane+2]=r[2]; dst[8*lane+3]=r[3];
                dst[8*lane+4]=r[4]; dst[8*lane+5]=r[5]; dst[8*lane+6]=r[6]; dst[8*lane+7]=r[7];
                dst[256+8*lane+0]=r[8];  dst[256+8*lane+1]=r[9];
                dst[256+8*lane+2]=r[10]; dst[256+8*lane+3]=r[11];
                dst[256+8*lane+4]=r[12]; dst[256+8*lane+5]=r[13];
                dst[256+8*lane+6]=r[14]; dst[256+8*lane+7]=r[15];
            }
            __syncthreads();

            float M = -CUDART_INF_F;
            #pragma unroll
            for (int w = 0; w < 16; w++) M = fmaxf(M, sm_m[w]);
            if (tid < 16)
                sm_scale[tid] = (sm_m[tid] == -CUDART_INF_F) ? 0.0f : __expf(sm_m[tid] - M);
            __syncthreads();

            float Dn = 0.0f, num = 0.0f;
            #pragma unroll
            for (int w = 0; w < 16; w++) {
                Dn  += sm_d[w] * sm_scale[w];
                num  = fmaf(((const float*)sm_r[w])[tid], sm_scale[w], num);
            }

            const int slot = chunk - g_off[b] / CHUNK;
            g_part_r[(b * MAX_SLOTS + slot) * D_IN + tid] = num;
            if (tid == 0) {
                g_part_m[b * MAX_SLOTS + slot] = M;
                g_part_d[b * MAX_SLOTS + slot] = Dn;
            }
            __syncthreads();
        }
        b++;
    }
}

// ------------------ attention pass 2: per-graph merge ------------------------
__global__ void attn_merge_kernel() {
    const int b   = blockIdx.x;
    const int tid = threadIdx.x;
    const int o0 = g_off[b], o1 = g_off[b + 1];
    if (o1 <= o0) { g_hr[b * 1024 + 512 + tid] = 0.0f; return; }
    const int J = (o1 - 1) / CHUNK - o0 / CHUNK + 1;

    float M = -CUDART_INF_F;
    for (int j = 0; j < J; j++) M = fmaxf(M, g_part_m[b * MAX_SLOTS + j]);
    float D = 0.0f, acc = 0.0f;
    for (int j = 0; j < J; j++) {
        const float s = __expf(g_part_m[b * MAX_SLOTS + j] - M);
        D   = fmaf(g_part_d[b * MAX_SLOTS + j], s, D);
        acc = fmaf(g_part_r[(b * MAX_SLOTS + j) * D_IN + tid], s, acc);
    }
    g_hr[b * 1024 + 512 + tid] = acc / (D + 1e-16f);
}

// ------------------------------- output --------------------------------------
__global__ void copyout_kernel(float* __restrict__ out) {
    int idx = blockIdx.x * blockDim.x + threadIdx.x;
    out[idx] = g_hr[idx];
}

// ------------------------------- launch --------------------------------------
extern "C" void kernel_launch(void* const* d_in, const int* in_sizes, int n_in,
                              void* d_out, int out_size) {
    const float* x     = (const float*)d_in[0];
    const int*   batch = (const int*)d_in[1];
    const float* w_ih  = (const float*)d_in[2];
    const float* w_hh  = (const float*)d_in[3];
    const float* b_ih  = (const float*)d_in[4];
    const float* b_hh  = (const float*)d_in[5];
    float* out = (float*)d_out;

    prep_w_kernel<<<(GATES * K_COMB) / 256, 256>>>(w_ih, w_hh, b_ih, b_hh);
    offsets_kernel<<<2, 160>>>(batch);
    lstm_init_kernel<<<B_GRAPHS, 512>>>();

    for (int s = 0; s < STEPS; s++) {
        if (s > 0) {
            gemm_tc_kernel<<<dim3(32, 4), 256>>>();
            lstm_pw_kernel<<<(B_GRAPHS * D_IN) / 512, 512>>>();
        }
        if (s == 0)
            attn0_kernel<<<N_CHUNKS, 512>>>(x);
        else
            attn16_kernel<<<N_CHUNKS, 512>>>();
        attn_merge_kernel<<<B_GRAPHS, 512>>>();
    }
    copyout_kernel<<<(B_GRAPHS * 1024) / 256, 256>>>(out);
}